// round 17
// baseline (speedup 1.0000x reference)
#include <cuda_runtime.h>
#include <math_constants.h>

// KNN min-dist, 9x9 window, C=3, zero-padded.
// d^2 = |t|^2 + (|o|^2 - 2 t.o), q=|o|^2 in float4.w -> 3 FFMA + 1 FMNMX/shift.
// R13 mainloop (flat (dj,r) unroll, LA=2 lookahead, dual min acc, 7 CTA/SM).
// Prologue vectorized: tile filled in 4-col chunks via LDG.128 (halo = exactly
// one chunk -> whole-vector edge predication), 6 LDG.128/thread vs 24 LDG.32.
// Fixed shapes: B=4, C=3, H=256, W=512.

#define BDIM 128
#define TW 32
#define TH 16
#define TY 4
#define HALO 4
#define SW 9

#define B_ 4
#define H_ 256
#define W_ 512
#define HW_ (H_*W_)

#define SH_H (TH + 2*HALO)   // 24
#define SH_W (TW + 2*HALO)   // 40
#define NR (TY + SW - 1)     // 12
#define NITER (SW * NR)      // 108
#define NCHUNK (SH_H * (SH_W/4))   // 24 rows * 10 chunks = 240

__global__ __launch_bounds__(BDIM, 7) void knn_min_kernel(
    const float* __restrict__ tfm, const float* __restrict__ obs,
    float* __restrict__ out)
{
    __shared__ float4 s4[SH_H][SH_W];   // (o0, o1, o2, |o|^2)

    const int b  = blockIdx.z;
    const int x0 = blockIdx.x * TW;
    const int y0 = blockIdx.y * TH;
    const int tid = threadIdx.x;
    const int tx = tid & 31;
    const int ty = tid >> 5;

    const float* obs_b = obs + b * 3 * HW_;
    const float* tfm_b = tfm + b * 3 * HW_;

    // ---- prologue: tfm LDGs first (longest dependence chain to mainloop) ----
    const int ybase = y0 + ty * TY;
    const int xg = x0 + tx;
    float ta[TY], tc[TY], te[TY];
#pragma unroll
    for (int k = 0; k < TY; k++) {
        int g = (ybase + k) * W_ + xg;
        ta[k] = tfm_b[g];
        tc[k] = tfm_b[HW_ + g];
        te[k] = tfm_b[2 * HW_ + g];
    }

    // ---- obs tile fill: 240 chunks of 4 cols; thread does chunks tid, tid+128.
    // Chunk c: row iy=c/10, col group jc=c%10, gmem base gx=x0-4+4*jc (16B
    // aligned since x0 % 32 == 0). Edge chunks (jc==0 / jc==9) are entirely
    // OOB when the block touches the image edge -> whole-vector predicate.
    float4 L[2][3];
    int cidx[2]; bool cok[2];
#pragma unroll
    for (int s = 0; s < 2; s++) {
        int c = tid + s * BDIM;
        cidx[s] = c;
        bool valid = (c < NCHUNK);
        int iy = c / 10;
        int jc = c - iy * 10;
        int gy = y0 - HALO + iy;
        int gx = x0 - HALO + 4 * jc;
        bool ok = valid & (gy >= 0) & (gy < H_)
                        & ((jc > 0) | (x0 > 0))
                        & ((jc < 9) | (x0 < W_ - TW));
        cok[s] = valid;
        const float4 z = make_float4(0.f, 0.f, 0.f, 0.f);
        if (ok) {
            int g = gy * W_ + gx;
            L[s][0] = *(const float4*)&obs_b[g];
            L[s][1] = *(const float4*)&obs_b[HW_ + g];
            L[s][2] = *(const float4*)&obs_b[2 * HW_ + g];
        } else {
            L[s][0] = z; L[s][1] = z; L[s][2] = z;
        }
    }
    // ---- q + transposed STS.128 (4 pixels per chunk) ----
#pragma unroll
    for (int s = 0; s < 2; s++) {
        if (cok[s]) {
            int c = cidx[s];
            int iy = c / 10;
            int jc = c - iy * 10;
            float o0[4] = {L[s][0].x, L[s][0].y, L[s][0].z, L[s][0].w};
            float o1[4] = {L[s][1].x, L[s][1].y, L[s][1].z, L[s][1].w};
            float o2[4] = {L[s][2].x, L[s][2].y, L[s][2].z, L[s][2].w};
#pragma unroll
            for (int l = 0; l < 4; l++) {
                float q = fmaf(o2[l], o2[l], fmaf(o1[l], o1[l], o0[l] * o0[l]));
                s4[iy][4 * jc + l] = make_float4(o0[l], o1[l], o2[l], q);
            }
        }
    }
    __syncthreads();

    // ---- per-pixel constants: nt_c = -2 t_c, tt = |t|^2 ----
    float nt0[TY], nt1[TY], nt2[TY], tt[TY], m0[TY], m1[TY];
#pragma unroll
    for (int k = 0; k < TY; k++) {
        nt0[k] = -2.f * ta[k];
        nt1[k] = -2.f * tc[k];
        nt2[k] = -2.f * te[k];
        tt[k]  = fmaf(te[k], te[k], fmaf(tc[k], tc[k], ta[k] * ta[k]));
        m0[k] = CUDART_INF_F;
        m1[k] = CUDART_INF_F;
    }

    // Flat base: iteration i -> dj = i/NR, r = i%NR, word offset r*SH_W + dj.
    const float4* base = &s4[ty * TY][tx];
#define OFF(i) (((i) % NR) * SH_W + ((i) / NR))

    float4 buf[3];
    buf[0] = base[OFF(0)];
    buf[1] = base[OFF(1)];

#pragma unroll
    for (int i = 0; i < NITER; i++) {
        if (i + 2 < NITER)
            buf[(i + 2) % 3] = base[OFF(i + 2)];
        const float4 v = buf[i % 3];
        const int dj = i / NR;
        const int r  = i % NR;
#pragma unroll
        for (int k = 0; k < TY; k++) {
            const int di = r - k;
            if (di >= 0 && di < SW) {
                float e = fmaf(nt0[k], v.x,
                          fmaf(nt1[k], v.y,
                          fmaf(nt2[k], v.z, v.w)));
                if (dj & 1) m1[k] = fminf(m1[k], e);
                else        m0[k] = fminf(m0[k], e);
            }
        }
    }
#undef OFF

    float* out_b = out + b * HW_;
#pragma unroll
    for (int k = 0; k < TY; k++) {
        float m = fminf(m0[k], m1[k]);
        out_b[(ybase + k) * W_ + xg] = sqrtf(fmaxf(tt[k] + m, 0.f));
    }
}

extern "C" void kernel_launch(void* const* d_in, const int* in_sizes, int n_in,
                              void* d_out, int out_size)
{
    const float* tfm = (const float*)d_in[0];
    const float* obs = (const float*)d_in[1];
    float* out = (float*)d_out;
    (void)in_sizes; (void)n_in; (void)out_size;

    dim3 grid(W_ / TW, H_ / TH, B_);   // 16 x 16 x 4 = 1024 blocks
    dim3 block(BDIM);
    knn_min_kernel<<<grid, block>>>(tfm, obs, out);
}